// round 13
// baseline (speedup 1.0000x reference)
#include <cuda_runtime.h>
#include <cuda_fp16.h>
#include <cstdint>

#define TPB 512

// smem layout
#define OF_WC 0u             // 32KB fp16 Wcf (128 rows x 256B, swizzled)
#define OF_WF 32768u         // 32KB fp16 Wfc
#define OF_WD 65536u         // 8KB  fp16 Wdf (128 rows x 64B, swizzled)
#define SLICE(q) (73728u + (uint32_t)(q) * 36864u)   // per-quad slice, 4 quads
//   +0     : fp16 src/h 64x128 (16KB), gate overwrites in place
//   +16384 : fp16 he 64x32 (4KB)
//   +20480 : fp32 staging S: 32 rows of src (16KB), double-pumped per tile
#define OF_BC 221184u
#define OF_BD 221696u
#define OF_BF 222208u
#define OF_MB 222720u        // 4 x 8B mbarriers
#define SMEM_BYTES 222752u

__device__ __forceinline__ void ldsm4(uint32_t r[4], uint32_t a) {
    asm volatile("ldmatrix.sync.aligned.m8n8.x4.shared.b16 {%0,%1,%2,%3}, [%4];"
                 : "=r"(r[0]), "=r"(r[1]), "=r"(r[2]), "=r"(r[3]) : "r"(a));
}

__device__ __forceinline__ void stsm4(uint32_t a, uint32_t r0, uint32_t r1,
                                      uint32_t r2, uint32_t r3) {
    asm volatile("stmatrix.sync.aligned.m8n8.x4.shared.b16 [%0], {%1,%2,%3,%4};"
                 :: "r"(a), "r"(r0), "r"(r1), "r"(r2), "r"(r3) : "memory");
}

__device__ __forceinline__ void mma16(float* c, const uint32_t* a, uint32_t b0, uint32_t b1) {
    asm volatile(
        "mma.sync.aligned.m16n8k16.row.col.f32.f16.f16.f32 "
        "{%0,%1,%2,%3}, {%4,%5,%6,%7}, {%8,%9}, {%0,%1,%2,%3};\n"
        : "+f"(c[0]), "+f"(c[1]), "+f"(c[2]), "+f"(c[3])
        : "r"(a[0]), "r"(a[1]), "r"(a[2]), "r"(a[3]), "r"(b0), "r"(b1));
}

// f16-accumulator mma — used for GEMM2 only (K=32, bias preloaded)
__device__ __forceinline__ void mma16h(uint32_t* c, const uint32_t* a, uint32_t b0, uint32_t b1) {
    asm volatile(
        "mma.sync.aligned.m16n8k16.row.col.f16.f16.f16.f16 "
        "{%0,%1}, {%2,%3,%4,%5}, {%6,%7}, {%0,%1};\n"
        : "+r"(c[0]), "+r"(c[1])
        : "r"(a[0]), "r"(a[1]), "r"(a[2]), "r"(a[3]), "r"(b0), "r"(b1));
}

__device__ __forceinline__ float ftanh(float x) {
    float r;
    asm("tanh.approx.f32 %0, %1;" : "=f"(r) : "f"(x));
    return r;
}

__device__ __forceinline__ uint32_t pack2(float a, float b) {
    __half2 h = __floats2half2_rn(a, b);
    return *(uint32_t*)&h;
}
__device__ __forceinline__ float2 unp2(uint32_t u) {
    __half2 h = *(__half2*)&u;
    return __half22float2(h);
}

// quad-scoped named barrier (128 threads)
__device__ __forceinline__ void qbar(int quad) {
    asm volatile("bar.sync %0, 128;" :: "r"(quad + 1) : "memory");
}

__device__ __forceinline__ void mb_init(uint32_t mbar, uint32_t cnt) {
    asm volatile("mbarrier.init.shared.b64 [%0], %1;" :: "r"(mbar), "r"(cnt) : "memory");
}
__device__ __forceinline__ void mb_expect(uint32_t mbar, uint32_t tx) {
    asm volatile("mbarrier.arrive.expect_tx.shared.b64 _, [%0], %1;"
                 :: "r"(mbar), "r"(tx) : "memory");
}
__device__ __forceinline__ void mb_wait(uint32_t mbar, uint32_t parity) {
    asm volatile("{\n\t.reg .pred P1;\n\t"
        "W_%=:\n\t"
        "mbarrier.try_wait.parity.acquire.cta.shared::cta.b64 P1, [%0], %1, 0x989680;\n\t"
        "@P1 bra.uni D_%=;\n\t"
        "bra.uni W_%=;\n\t"
        "D_%=:\n\t}"
        :: "r"(mbar), "r"(parity) : "memory");
}
__device__ __forceinline__ void bulk_g2s(uint32_t dst, const void* src,
                                         uint32_t bytes, uint32_t mbar) {
    asm volatile("cp.async.bulk.shared::cta.global.mbarrier::complete_tx::bytes "
                 "[%0], [%1], %2, [%3];"
                 :: "r"(dst), "l"(src), "r"(bytes), "r"(mbar) : "memory");
}
#define PROXY_FENCE() asm volatile("fence.proxy.async.shared::cta;" ::: "memory")

// 256B-row swizzled addr (128 fp16 cols): ch 0..15
__device__ __forceinline__ uint32_t a16(uint32_t row, uint32_t ch) {
    return row * 256u + ((ch ^ (row & 7u)) << 4);
}
// 64B-row swizzled addr (32 fp16 cols): ch 0..3
__device__ __forceinline__ uint32_t h16(uint32_t row, uint32_t ch) {
    return row * 64u + ((ch ^ ((row >> 1) & 3u)) << 4);
}

__global__ void __launch_bounds__(TPB, 1)
dtnn_kernel(const float* __restrict__ gsrc, const float* __restrict__ ghe,
            const float* __restrict__ Wcf,  const float* __restrict__ bcf,
            const float* __restrict__ Wdf,  const float* __restrict__ bdf,
            const float* __restrict__ Wfc,  const float* __restrict__ bfc,
            float* __restrict__ out, int ntiles)
{
    extern __shared__ __align__(1024) unsigned char sm[];
    uint32_t smb;
    asm("{.reg .u64 t; cvta.to.shared.u64 t, %1; cvt.u32.u64 %0, t;}"
        : "=r"(smb) : "l"(sm));

    float* bC = (float*)(sm + OF_BC);
    float* bD = (float*)(sm + OF_BD);
    float* bF = (float*)(sm + OF_BF);

    const int tid  = threadIdx.x;
    const int lane = tid & 31;
    const int wid  = tid >> 5;
    const int tg   = lane & 3;
    const int quad = wid >> 2;            // owns 64 rows (2 nodes) per tile
    const int qtid = tid & 127;
    const int n0   = (wid & 3) * 32;      // column quarter
    const uint32_t mbar = smb + OF_MB + (uint32_t)quad * 8u;
    const int grid = gridDim.x;

    // ---- mbarrier init ----
    if (tid < 4) {
        mb_init(smb + OF_MB + (uint32_t)tid * 8u, 1u);
        PROXY_FENCE();
    }
    __syncthreads();

    // ---- prologue: bulk half0 of tile0 + hold he(tile0) in registers ----
    float4 hv[4];
    if (blockIdx.x < ntiles) {
        if (qtid == 0) {
            mb_expect(mbar, 16384u);
            bulk_g2s(smb + (SLICE(quad) - 0u) + 20480u,
                     gsrc + (size_t)blockIdx.x * 32768 + quad * 8192, 16384u, mbar);
        }
        const float4* hp = (const float4*)(ghe + (size_t)blockIdx.x * 8192 + quad * 2048);
        #pragma unroll
        for (int it = 0; it < 2; it++) {
            int j = qtid + it * 128;
            hv[2 * it]     = hp[2 * j];
            hv[2 * it + 1] = hp[2 * j + 1];
        }
    }

    // ---- one-time weight + bias staging ----
    for (int i = tid; i < 2048; i += TPB) {
        int row = i >> 4, ch = i & 15;
        float4 u = ((const float4*)Wcf)[row * 32 + ch * 2];
        float4 v = ((const float4*)Wcf)[row * 32 + ch * 2 + 1];
        uint4 w = {pack2(u.x, u.y), pack2(u.z, u.w), pack2(v.x, v.y), pack2(v.z, v.w)};
        *(uint4*)(sm + OF_WC + a16(row, ch)) = w;
        u = ((const float4*)Wfc)[row * 32 + ch * 2];
        v = ((const float4*)Wfc)[row * 32 + ch * 2 + 1];
        uint4 w2 = {pack2(u.x, u.y), pack2(u.z, u.w), pack2(v.x, v.y), pack2(v.z, v.w)};
        *(uint4*)(sm + OF_WF + a16(row, ch)) = w2;
    }
    for (int i = tid; i < 512; i += TPB) {
        int row = i >> 2, ch = i & 3;
        float4 u = ((const float4*)Wdf)[row * 8 + ch * 2];
        float4 v = ((const float4*)Wdf)[row * 8 + ch * 2 + 1];
        uint4 w = {pack2(u.x, u.y), pack2(u.z, u.w), pack2(v.x, v.y), pack2(v.z, v.w)};
        *(uint4*)(sm + OF_WD + h16(row, ch)) = w;
    }
    if (tid < 128) { bC[tid] = bcf[tid]; bD[tid] = bdf[tid]; bF[tid] = bfc[tid]; }
    __syncthreads();

    // ---- per-lane ldmatrix constants ----
    const uint32_t mrow = (uint32_t)((lane & 7) | (((lane >> 3) & 1) << 3));
    const uint32_t ksel = (uint32_t)((lane >> 4) & 1);
    const uint32_t key8 = mrow & 7u;
    const uint32_t keyh = (mrow >> 1) & 3u;

    const uint32_t slice = smb + SLICE(quad);
    const uint32_t srcB = slice + mrow * 256u;           // +mt*4096 for rows 16mt..
    const uint32_t heB  = slice + 16384u + mrow * 64u;   // +mt*1024
    const uint32_t stg  = slice + 20480u;
    const uint32_t wc0  = smb + OF_WC + ((uint32_t)n0 + mrow) * 256u;  // +4096 for p=1
    const uint32_t wf0  = smb + OF_WF + ((uint32_t)n0 + mrow) * 256u;
    const uint32_t wd0  = smb + OF_WD + ((uint32_t)n0 + mrow) * 64u;   // +1024 for p=1
    const uint32_t srow = (uint32_t)(((lane >> 4) & 1) * 16 + ((lane >> 3) & 1) * 8
                                     + (lane & 7));

    uint32_t ph = 0;

    for (int c = blockIdx.x; c < ntiles; c += grid) {
        // 1. half0 arrived (prefetched during prev tile); prev tile fully done
        mb_wait(mbar, ph); ph ^= 1;
        qbar(quad);

        // 2. convert half0 (rows 0-31) + he (from held regs) -> fp16 swizzled
        {
            const float4* sg = (const float4*)(sm + (stg - smb));
            #pragma unroll
            for (int it = 0; it < 4; it++) {
                int i = qtid + it * 128;           // 512 16B chunks
                int row = i >> 4, ch = i & 15;
                float4 u = sg[row * 32 + ch * 2];
                float4 v = sg[row * 32 + ch * 2 + 1];
                uint4 w = {pack2(u.x, u.y), pack2(u.z, u.w),
                           pack2(v.x, v.y), pack2(v.z, v.w)};
                *(uint4*)(sm + (slice - smb) + a16((uint32_t)row, (uint32_t)ch)) = w;
            }
            #pragma unroll
            for (int it = 0; it < 2; it++) {
                int j = qtid + it * 128;           // 256 16B out-chunks
                int row = j >> 2, ch = j & 3;
                float4 u = hv[2 * it];
                float4 v = hv[2 * it + 1];
                uint4 w = {pack2(u.x, u.y), pack2(u.z, u.w),
                           pack2(v.x, v.y), pack2(v.z, v.w)};
                *(uint4*)(sm + (slice - smb) + 16384u
                          + h16((uint32_t)row, (uint32_t)ch)) = w;
            }
        }
        qbar(quad);    // half0+he fp16 visible; staging free

        // 3. bulk half1 (rows 32-63)
        if (qtid == 0) {
            PROXY_FENCE();
            mb_expect(mbar, 16384u);
            bulk_g2s(stg, gsrc + (size_t)c * 32768 + quad * 8192 + 4096, 16384u, mbar);
        }

        // 4. GEMM2 (f16 acc): accEp = he @ Wdf^T + bdf (covers half1 latency)
        uint32_t accEp[4][4][2];
        {
            uint32_t bini[4];
            #pragma unroll
            for (int nt = 0; nt < 4; nt++) {
                int cc = n0 + nt * 8 + 2 * tg;
                float2 bd2 = *(float2*)(bD + cc);
                bini[nt] = pack2(bd2.x, bd2.y);
            }
            #pragma unroll
            for (int mt = 0; mt < 4; mt++)
                #pragma unroll
                for (int nt = 0; nt < 4; nt++) {
                    accEp[mt][nt][0] = bini[nt];
                    accEp[mt][nt][1] = bini[nt];
                }
            #pragma unroll
            for (int kt = 0; kt < 2; kt++) {
                uint32_t ua = ((2u * kt + ksel) ^ keyh) << 4;
                uint32_t D0[4], D1[4];
                ldsm4(D0, wd0 + ua);
                ldsm4(D1, wd0 + 1024u + ua);
                #pragma unroll
                for (int mt = 0; mt < 4; mt++) {
                    uint32_t A[4];
                    ldsm4(A, heB + (uint32_t)mt * 1024u + ua);
                    mma16h(accEp[mt][0], A, D0[0], D0[2]);
                    mma16h(accEp[mt][1], A, D0[1], D0[3]);
                    mma16h(accEp[mt][2], A, D1[0], D1[2]);
                    mma16h(accEp[mt][3], A, D1[1], D1[3]);
                }
            }
        }

        // 5. half1 arrived -> convert (rows 32-63)
        mb_wait(mbar, ph); ph ^= 1;
        {
            const float4* sg = (const float4*)(sm + (stg - smb));
            #pragma unroll
            for (int it = 0; it < 4; it++) {
                int i = qtid + it * 128;
                int row = i >> 4, ch = i & 15;
                float4 u = sg[row * 32 + ch * 2];
                float4 v = sg[row * 32 + ch * 2 + 1];
                uint4 w = {pack2(u.x, u.y), pack2(u.z, u.w),
                           pack2(v.x, v.y), pack2(v.z, v.w)};
                *(uint4*)(sm + (slice - smb) + a16((uint32_t)(row + 32), (uint32_t)ch)) = w;
            }
        }
        qbar(quad);    // src fully visible; staging free

        // 6. prefetch next tile half0 (bulk only; he LDG deferred to post-gate)
        if (qtid == 0 && c + grid < ntiles) {
            PROXY_FENCE();
            mb_expect(mbar, 16384u);
            bulk_g2s(stg, gsrc + (size_t)(c + grid) * 32768 + quad * 8192,
                     16384u, mbar);
        }

        // 7. GEMM1: accC = src @ Wcf^T  (64x32 per warp)
        float accC[4][4][4];
        #pragma unroll
        for (int mt = 0; mt < 4; mt++)
            #pragma unroll
            for (int nt = 0; nt < 4; nt++)
                accC[mt][nt][0] = accC[mt][nt][1] = accC[mt][nt][2] = accC[mt][nt][3] = 0.f;
        #pragma unroll
        for (int kt = 0; kt < 8; kt++) {
            uint32_t ua = ((2u * kt + ksel) ^ key8) << 4;
            uint32_t B0[4], B1[4];
            ldsm4(B0, wc0 + ua);
            ldsm4(B1, wc0 + 4096u + ua);
            #pragma unroll
            for (int mt = 0; mt < 4; mt++) {
                uint32_t A[4];
                ldsm4(A, srcB + (uint32_t)mt * 4096u + ua);
                mma16(accC[mt][0], A, B0[0], B0[2]);
                mma16(accC[mt][1], A, B0[1], B0[3]);
                mma16(accC[mt][2], A, B1[0], B1[2]);
                mma16(accC[mt][3], A, B1[1], B1[3]);
            }
        }
        qbar(quad);    // all warps done reading src before in-place gate

        // 8. gate: h = (c + bcf) * e  written in place over src (stmatrix)
        #pragma unroll
        for (int mtp = 0; mtp < 2; mtp++) {
            #pragma unroll
            for (int nt = 0; nt < 4; nt++) {
                int cc = n0 + nt * 8 + 2 * tg;
                float2 bc2 = *(float2*)(bC + cc);
                int mA = 2 * mtp, mB = 2 * mtp + 1;
                float2 eA0 = unp2(accEp[mA][nt][0]);
                float2 eA1 = unp2(accEp[mA][nt][1]);
                float2 eB0 = unp2(accEp[mB][nt][0]);
                float2 eB1 = unp2(accEp[mB][nt][1]);
                uint32_t p0 = pack2((accC[mA][nt][0] + bc2.x) * eA0.x,
                                    (accC[mA][nt][1] + bc2.y) * eA0.y);
                uint32_t p1 = pack2((accC[mA][nt][2] + bc2.x) * eA1.x,
                                    (accC[mA][nt][3] + bc2.y) * eA1.y);
                uint32_t p2 = pack2((accC[mB][nt][0] + bc2.x) * eB0.x,
                                    (accC[mB][nt][1] + bc2.y) * eB0.y);
                uint32_t p3 = pack2((accC[mB][nt][2] + bc2.x) * eB1.x,
                                    (accC[mB][nt][3] + bc2.y) * eB1.y);
                uint32_t ch = (uint32_t)(n0 >> 3) + (uint32_t)nt;
                stsm4(slice + a16(srow + (uint32_t)mtp * 32u, ch), p0, p1, p2, p3);
            }
        }
        qbar(quad);    // h visible

        // 9. he prefetch for next tile (accEp now dead -> 16 regs fit)
        if (c + grid < ntiles) {
            const float4* hp = (const float4*)(ghe + (size_t)(c + grid) * 8192
                                               + quad * 2048);
            #pragma unroll
            for (int it = 0; it < 2; it++) {
                int j = qtid + it * 128;
                hv[2 * it]     = hp[2 * j];
                hv[2 * it + 1] = hp[2 * j + 1];
            }
        }

        // 10. GEMM3: accO = h @ Wfc^T (reuse accC)
        #pragma unroll
        for (int mt = 0; mt < 4; mt++)
            #pragma unroll
            for (int nt = 0; nt < 4; nt++)
                accC[mt][nt][0] = accC[mt][nt][1] = accC[mt][nt][2] = accC[mt][nt][3] = 0.f;
        #pragma unroll
        for (int kt = 0; kt < 8; kt++) {
            uint32_t ua = ((2u * kt + ksel) ^ key8) << 4;
            uint32_t B0[4], B1[4];
            ldsm4(B0, wf0 + ua);
            ldsm4(B1, wf0 + 4096u + ua);
            #pragma unroll
            for (int mt = 0; mt < 4; mt++) {
                uint32_t A[4];
                ldsm4(A, srcB + (uint32_t)mt * 4096u + ua);
                mma16(accC[mt][0], A, B0[0], B0[2]);
                mma16(accC[mt][1], A, B0[1], B0[3]);
                mma16(accC[mt][2], A, B1[0], B1[2]);
                mma16(accC[mt][3], A, B1[1], B1[3]);
            }
        }

        // 11. epilogue: tanh + mailbox reduce; 2 nodes per tile-slice
        #pragma unroll
        for (int nd = 0; nd < 2; nd++) {
            const int node = c * 8 + quad * 2 + nd;
            const int mA = 2 * nd, mB = 2 * nd + 1;
            float v[8];
            #pragma unroll
            for (int nt = 0; nt < 4; nt++) {
                int cc = n0 + nt * 8 + 2 * tg;
                float2 bf2 = *(float2*)(bF + cc);
                v[2 * nt]     = ftanh(accC[mA][nt][0] + bf2.x) + ftanh(accC[mA][nt][2] + bf2.x)
                              + ftanh(accC[mB][nt][0] + bf2.x) + ftanh(accC[mB][nt][2] + bf2.x);
                v[2 * nt + 1] = ftanh(accC[mA][nt][1] + bf2.y) + ftanh(accC[mA][nt][3] + bf2.y)
                              + ftanh(accC[mB][nt][1] + bf2.y) + ftanh(accC[mB][nt][3] + bf2.y);
            }
            #pragma unroll
            for (int m = 4; m < 32; m <<= 1) {
                #pragma unroll
                for (int i = 0; i < 8; i++)
                    v[i] += __shfl_xor_sync(0xffffffffu, v[i], m);
            }
            if (lane < 4) {
                #pragma unroll
                for (int nt = 0; nt < 4; nt++) {
                    float2 o = {v[2 * nt], v[2 * nt + 1]};
                    *(float2*)(out + (size_t)node * 128 + n0 + nt * 8 + 2 * tg) = o;
                }
            }
        }
    }
}

extern "C" void kernel_launch(void* const* d_in, const int* in_sizes, int n_in,
                              void* d_out, int out_size)
{
    const float* src = (const float*)d_in[0];
    const float* he  = (const float*)d_in[1];
    const float* Wcf = (const float*)d_in[2];
    const float* bcf = (const float*)d_in[3];
    const float* Wdf = (const float*)d_in[4];
    const float* bdf = (const float*)d_in[5];
    const float* Wfc = (const float*)d_in[6];
    const float* bfc = (const float*)d_in[7];
    float* out = (float*)d_out;

    int ntiles = in_sizes[0] / 32768;   // 256 pairs (8 nodes) per tile

    int nsm = 148;
    cudaDeviceGetAttribute(&nsm, cudaDevAttrMultiProcessorCount, 0);
    int grid = nsm < ntiles ? nsm : ntiles;

    cudaFuncSetAttribute(dtnn_kernel, cudaFuncAttributeMaxDynamicSharedMemorySize,
                         (int)SMEM_BYTES);
    dtnn_kernel<<<grid, TPB, SMEM_BYTES>>>(src, he, Wcf, bcf, Wdf, bdf, Wfc, bfc,
                                           out, ntiles);
}

// round 14
// speedup vs baseline: 1.2002x; 1.2002x over previous
#include <cuda_runtime.h>
#include <cuda_fp16.h>
#include <cstdint>

#define TPB 512

// smem byte offsets
#define OF_WC   0u           // 32KB fp16 Wcf (128 rows x 256B, swizzled)
#define OF_WF   32768u       // 32KB fp16 Wfc
#define OF_WD   65536u       // 8KB fp16 Wdf (hoisted to regs at init)
#define OF_SRCq(q) (73728u  + (uint32_t)(q) * 8192u)   // fp16 src slice: 32x128
#define OF_HEq(q)  (106496u + (uint32_t)(q) * 2048u)   // fp16 he slice: 32x32
#define OF_Hq(q)   (114688u + (uint32_t)(q) * 8192u)   // fp16 h slice: 32x128
#define OF_SG(q)   (147456u + (uint32_t)(q) * 16384u)  // fp32 staging src
#define OF_SGH(q)  (212992u + (uint32_t)(q) * 4096u)   // fp32 staging he
#define OF_BC   229376u
#define OF_BD   229888u
#define OF_BF   230400u
#define OF_MB   230912u      // 4 x 8B mbarriers
#define SMEM_BYTES 230976u

__device__ __forceinline__ void ldsm4(uint32_t r[4], uint32_t a) {
    asm volatile("ldmatrix.sync.aligned.m8n8.x4.shared.b16 {%0,%1,%2,%3}, [%4];"
                 : "=r"(r[0]), "=r"(r[1]), "=r"(r[2]), "=r"(r[3]) : "r"(a));
}

__device__ __forceinline__ void stsm4(uint32_t a, uint32_t r0, uint32_t r1,
                                      uint32_t r2, uint32_t r3) {
    asm volatile("stmatrix.sync.aligned.m8n8.x4.shared.b16 [%0], {%1,%2,%3,%4};"
                 :: "r"(a), "r"(r0), "r"(r1), "r"(r2), "r"(r3) : "memory");
}

__device__ __forceinline__ void mma16(float* c, const uint32_t* a, uint32_t b0, uint32_t b1) {
    asm volatile(
        "mma.sync.aligned.m16n8k16.row.col.f32.f16.f16.f32 "
        "{%0,%1,%2,%3}, {%4,%5,%6,%7}, {%8,%9}, {%0,%1,%2,%3};\n"
        : "+f"(c[0]), "+f"(c[1]), "+f"(c[2]), "+f"(c[3])
        : "r"(a[0]), "r"(a[1]), "r"(a[2]), "r"(a[3]), "r"(b0), "r"(b1));
}

// f16-accumulator mma — GEMM2 only (K=32, bias preloaded into acc)
__device__ __forceinline__ void mma16h(uint32_t* c, const uint32_t* a, uint32_t b0, uint32_t b1) {
    asm volatile(
        "mma.sync.aligned.m16n8k16.row.col.f16.f16.f16.f16 "
        "{%0,%1}, {%2,%3,%4,%5}, {%6,%7}, {%0,%1};\n"
        : "+r"(c[0]), "+r"(c[1])
        : "r"(a[0]), "r"(a[1]), "r"(a[2]), "r"(a[3]), "r"(b0), "r"(b1));
}

__device__ __forceinline__ float ftanh(float x) {
    float r;
    asm("tanh.approx.f32 %0, %1;" : "=f"(r) : "f"(x));
    return r;
}

__device__ __forceinline__ uint32_t pack2(float a, float b) {
    __half2 h = __floats2half2_rn(a, b);
    return *(uint32_t*)&h;
}
__device__ __forceinline__ float2 unp2(uint32_t u) {
    __half2 h = *(__half2*)&u;
    return __half22float2(h);
}

__device__ __forceinline__ void qbar(int quad) {
    asm volatile("bar.sync %0, 128;" :: "r"(quad + 1) : "memory");
}

__device__ __forceinline__ void mb_init(uint32_t mbar, uint32_t cnt) {
    asm volatile("mbarrier.init.shared.b64 [%0], %1;" :: "r"(mbar), "r"(cnt) : "memory");
}
__device__ __forceinline__ void mb_expect(uint32_t mbar, uint32_t tx) {
    asm volatile("mbarrier.arrive.expect_tx.shared.b64 _, [%0], %1;"
                 :: "r"(mbar), "r"(tx) : "memory");
}
__device__ __forceinline__ void mb_wait(uint32_t mbar, uint32_t parity) {
    asm volatile("{\n\t.reg .pred P1;\n\t"
        "W_%=:\n\t"
        "mbarrier.try_wait.parity.acquire.cta.shared::cta.b64 P1, [%0], %1, 0x989680;\n\t"
        "@P1 bra.uni D_%=;\n\t"
        "bra.uni W_%=;\n\t"
        "D_%=:\n\t}"
        :: "r"(mbar), "r"(parity) : "memory");
}
__device__ __forceinline__ void bulk_g2s(uint32_t dst, const void* src,
                                         uint32_t bytes, uint32_t mbar) {
    asm volatile("cp.async.bulk.shared::cta.global.mbarrier::complete_tx::bytes "
                 "[%0], [%1], %2, [%3];"
                 :: "r"(dst), "l"(src), "r"(bytes), "r"(mbar) : "memory");
}
#define PROXY_FENCE() asm volatile("fence.proxy.async.shared::cta;" ::: "memory")

__device__ __forceinline__ uint32_t a16(uint32_t row, uint32_t ch) {
    return row * 256u + ((ch ^ (row & 7u)) << 4);
}
__device__ __forceinline__ uint32_t h16(uint32_t row, uint32_t ch) {
    return row * 64u + ((ch ^ ((row >> 1) & 3u)) << 4);
}

__global__ void __launch_bounds__(TPB, 1)
dtnn_kernel(const float* __restrict__ gsrc, const float* __restrict__ ghe,
            const float* __restrict__ Wcf,  const float* __restrict__ bcf,
            const float* __restrict__ Wdf,  const float* __restrict__ bdf,
            const float* __restrict__ Wfc,  const float* __restrict__ bfc,
            float* __restrict__ out, int ntiles)
{
    extern __shared__ __align__(1024) unsigned char sm[];
    uint32_t smb;
    asm("{.reg .u64 t; cvta.to.shared.u64 t, %1; cvt.u32.u64 %0, t;}"
        : "=r"(smb) : "l"(sm));

    float* bC = (float*)(sm + OF_BC);
    float* bD = (float*)(sm + OF_BD);
    float* bF = (float*)(sm + OF_BF);

    const int tid  = threadIdx.x;
    const int lane = tid & 31;
    const int wid  = tid >> 5;
    const int tg   = lane & 3;
    const int quad = wid >> 2;
    const int qtid = tid & 127;
    const int n0   = (wid & 3) * 32;
    const uint32_t mbar = smb + OF_MB + (uint32_t)quad * 8u;
    const int grid = gridDim.x;

    if (tid < 4) {
        mb_init(smb + OF_MB + (uint32_t)tid * 8u, 1u);
        PROXY_FENCE();
    }
    __syncthreads();

    if (qtid == 0) {
        mb_expect(mbar, 20480u);
        bulk_g2s(smb + OF_SG(quad), gsrc + (size_t)blockIdx.x * 16384 + quad * 4096,
                 16384u, mbar);
        bulk_g2s(smb + OF_SGH(quad), ghe + (size_t)blockIdx.x * 4096 + quad * 1024,
                 4096u, mbar);
    }

    for (int i = tid; i < 2048; i += TPB) {
        int row = i >> 4, ch = i & 15;
        float4 u = ((const float4*)Wcf)[row * 32 + ch * 2];
        float4 v = ((const float4*)Wcf)[row * 32 + ch * 2 + 1];
        uint4 w = {pack2(u.x, u.y), pack2(u.z, u.w), pack2(v.x, v.y), pack2(v.z, v.w)};
        *(uint4*)(sm + OF_WC + a16(row, ch)) = w;
        u = ((const float4*)Wfc)[row * 32 + ch * 2];
        v = ((const float4*)Wfc)[row * 32 + ch * 2 + 1];
        uint4 w2 = {pack2(u.x, u.y), pack2(u.z, u.w), pack2(v.x, v.y), pack2(v.z, v.w)};
        *(uint4*)(sm + OF_WF + a16(row, ch)) = w2;
    }
    for (int i = tid; i < 512; i += TPB) {
        int row = i >> 2, ch = i & 3;
        float4 u = ((const float4*)Wdf)[row * 8 + ch * 2];
        float4 v = ((const float4*)Wdf)[row * 8 + ch * 2 + 1];
        uint4 w = {pack2(u.x, u.y), pack2(u.z, u.w), pack2(v.x, v.y), pack2(v.z, v.w)};
        *(uint4*)(sm + OF_WD + h16(row, ch)) = w;
    }
    if (tid < 128) { bC[tid] = bcf[tid]; bD[tid] = bdf[tid]; bF[tid] = bfc[tid]; }
    __syncthreads();

    const uint32_t mrow = (uint32_t)((lane & 7) | (((lane >> 3) & 1) << 3));
    const uint32_t ksel = (uint32_t)((lane >> 4) & 1);
    const uint32_t key8 = mrow & 7u;
    const uint32_t keyh = (mrow >> 1) & 3u;

    const uint32_t srcB = smb + OF_SRCq(quad) + mrow * 256u;
    const uint32_t heB  = smb + OF_HEq(quad) + mrow * 64u;
    const uint32_t hBa  = smb + OF_Hq(quad) + mrow * 256u;
    const uint32_t hBst = smb + OF_Hq(quad);
    const uint32_t wc0  = smb + OF_WC + ((uint32_t)n0 + mrow) * 256u;
    const uint32_t wf0  = smb + OF_WF + ((uint32_t)n0 + mrow) * 256u;
    uint32_t wdr[2][2][4];
    {
        uint32_t wdB[2];
        #pragma unroll
        for (int p = 0; p < 2; p++)
            wdB[p] = smb + OF_WD + ((uint32_t)(n0 + 16 * p) + mrow) * 64u;
        #pragma unroll
        for (int kt = 0; kt < 2; kt++) {
            uint32_t ub = ((2u * kt + ksel) ^ keyh) << 4;
            ldsm4(wdr[kt][0], wdB[0] + ub);
            ldsm4(wdr[kt][1], wdB[1] + ub);
        }
    }
    const uint32_t srow = (uint32_t)(((lane >> 4) & 1) * 16 + ((lane >> 3) & 1) * 8
                                     + (lane & 7));

    uint32_t ph = 0;

    for (int tile = blockIdx.x; tile < ntiles; tile += grid) {
        mb_wait(mbar, ph); ph ^= 1;
        qbar(quad);

        {
            const float4* sg = (const float4*)(sm + OF_SG(quad));
            #pragma unroll
            for (int it = 0; it < 4; it++) {
                int i = qtid + it * 128;
                int row = i >> 4, ch = i & 15;
                float4 u = sg[row * 32 + ch * 2];
                float4 v = sg[row * 32 + ch * 2 + 1];
                uint4 w = {pack2(u.x, u.y), pack2(u.z, u.w),
                           pack2(v.x, v.y), pack2(v.z, v.w)};
                *(uint4*)(sm + OF_SRCq(quad) + a16((uint32_t)row, (uint32_t)ch)) = w;
            }
            const float4* sh = (const float4*)(sm + OF_SGH(quad));
            {
                int i = qtid;
                int row = i >> 2, ch = i & 3;
                float4 u = sh[row * 8 + ch * 2];
                float4 v = sh[row * 8 + ch * 2 + 1];
                uint4 w = {pack2(u.x, u.y), pack2(u.z, u.w),
                           pack2(v.x, v.y), pack2(v.z, v.w)};
                *(uint4*)(sm + OF_HEq(quad) + h16((uint32_t)row, (uint32_t)ch)) = w;
            }
        }
        qbar(quad);

        if (qtid == 0 && tile + grid < ntiles) {
            int nt_ = tile + grid;
            PROXY_FENCE();
            mb_expect(mbar, 20480u);
            bulk_g2s(smb + OF_SG(quad), gsrc + (size_t)nt_ * 16384 + quad * 4096,
                     16384u, mbar);
            bulk_g2s(smb + OF_SGH(quad), ghe + (size_t)nt_ * 4096 + quad * 1024,
                     4096u, mbar);
        }

        // GEMM2 (f16 acc, bias preloaded)
        uint32_t accEp[2][4][2];
        #pragma unroll
        for (int nt = 0; nt < 4; nt++) {
            int c = n0 + nt * 8 + 2 * tg;
            float2 bd2 = *(float2*)(bD + c);
            uint32_t bini = pack2(bd2.x, bd2.y);
            accEp[0][nt][0] = bini; accEp[0][nt][1] = bini;
            accEp[1][nt][0] = bini; accEp[1][nt][1] = bini;
        }
        #pragma unroll
        for (int kt = 0; kt < 2; kt++) {
            uint32_t ua = ((2u * kt + ksel) ^ keyh) << 4;
            uint32_t A0[4], A1[4];
            ldsm4(A0, heB + ua);
            ldsm4(A1, heB + 1024u + ua);
            #pragma unroll
            for (int p = 0; p < 2; p++) {
                mma16h(accEp[0][2 * p],     A0, wdr[kt][p][0], wdr[kt][p][2]);
                mma16h(accEp[0][2 * p + 1], A0, wdr[kt][p][1], wdr[kt][p][3]);
                mma16h(accEp[1][2 * p],     A1, wdr[kt][p][0], wdr[kt][p][2]);
                mma16h(accEp[1][2 * p + 1], A1, wdr[kt][p][1], wdr[kt][p][3]);
            }
        }

        // GEMM1
        float accC[2][4][4];
        #pragma unroll
        for (int mt = 0; mt < 2; mt++)
            #pragma unroll
            for (int nt = 0; nt < 4; nt++)
                accC[mt][nt][0] = accC[mt][nt][1] = accC[mt][nt][2] = accC[mt][nt][3] = 0.f;
        #pragma unroll
        for (int kt = 0; kt < 8; kt++) {
            uint32_t ua = ((2u * kt + ksel) ^ key8) << 4;
            uint32_t A0[4], A1[4], B0[4], B1[4];
            ldsm4(A0, srcB + ua);
            ldsm4(A1, srcB + 4096u + ua);
            ldsm4(B0, wc0 + ua);
            ldsm4(B1, wc0 + 4096u + ua);
            mma16(accC[0][0], A0, B0[0], B0[2]);
            mma16(accC[0][1], A0, B0[1], B0[3]);
            mma16(accC[0][2], A0, B1[0], B1[2]);
            mma16(accC[0][3], A0, B1[1], B1[3]);
            mma16(accC[1][0], A1, B0[0], B0[2]);
            mma16(accC[1][1], A1, B0[1], B0[3]);
            mma16(accC[1][2], A1, B1[0], B1[2]);
            mma16(accC[1][3], A1, B1[1], B1[3]);
        }

        // gate -> h buffer
        #pragma unroll
        for (int nt = 0; nt < 4; nt++) {
            int c = n0 + nt * 8 + 2 * tg;
            float2 bc2 = *(float2*)(bC + c);
            float2 e00 = unp2(accEp[0][nt][0]);
            float2 e01 = unp2(accEp[0][nt][1]);
            float2 e10 = unp2(accEp[1][nt][0]);
            float2 e11 = unp2(accEp[1][nt][1]);
            uint32_t p0 = pack2((accC[0][nt][0] + bc2.x) * e00.x,
                                (accC[0][nt][1] + bc2.y) * e00.y);
            uint32_t p1 = pack2((accC[0][nt][2] + bc2.x) * e01.x,
                                (accC[0][nt][3] + bc2.y) * e01.y);
            uint32_t p2 = pack2((accC[1][nt][0] + bc2.x) * e10.x,
                                (accC[1][nt][1] + bc2.y) * e10.y);
            uint32_t p3 = pack2((accC[1][nt][2] + bc2.x) * e11.x,
                                (accC[1][nt][3] + bc2.y) * e11.y);
            uint32_t ch = (uint32_t)(n0 >> 3) + (uint32_t)nt;
            stsm4(hBst + a16(srow, ch), p0, p1, p2, p3);
        }
        qbar(quad);

        // GEMM3
        #pragma unroll
        for (int mt = 0; mt < 2; mt++)
            #pragma unroll
            for (int nt = 0; nt < 4; nt++)
                accC[mt][nt][0] = accC[mt][nt][1] = accC[mt][nt][2] = accC[mt][nt][3] = 0.f;
        #pragma unroll
        for (int kt = 0; kt < 8; kt++) {
            uint32_t ua = ((2u * kt + ksel) ^ key8) << 4;
            uint32_t A0[4], A1[4], B0[4], B1[4];
            ldsm4(A0, hBa + ua);
            ldsm4(A1, hBa + 4096u + ua);
            ldsm4(B0, wf0 + ua);
            ldsm4(B1, wf0 + 4096u + ua);
            mma16(accC[0][0], A0, B0[0], B0[2]);
            mma16(accC[0][1], A0, B0[1], B0[3]);
            mma16(accC[0][2], A0, B1[0], B1[2]);
            mma16(accC[0][3], A0, B1[1], B1[3]);
            mma16(accC[1][0], A1, B0[0], B0[2]);
            mma16(accC[1][1], A1, B0[1], B0[3]);
            mma16(accC[1][2], A1, B1[0], B1[2]);
            mma16(accC[1][3], A1, B1[1], B1[3]);
        }

        // epilogue
        {
            const int node = tile * 4 + quad;
            float v[8];
            #pragma unroll
            for (int nt = 0; nt < 4; nt++) {
                int c = n0 + nt * 8 + 2 * tg;
                float2 bf2 = *(float2*)(bF + c);
                v[2 * nt]     = ftanh(accC[0][nt][0] + bf2.x) + ftanh(accC[0][nt][2] + bf2.x)
                              + ftanh(accC[1][nt][0] + bf2.x) + ftanh(accC[1][nt][2] + bf2.x);
                v[2 * nt + 1] = ftanh(accC[0][nt][1] + bf2.y) + ftanh(accC[0][nt][3] + bf2.y)
                              + ftanh(accC[1][nt][1] + bf2.y) + ftanh(accC[1][nt][3] + bf2.y);
            }
            #pragma unroll
            for (int m = 4; m < 32; m <<= 1) {
                #pragma unroll
                for (int i = 0; i < 8; i++)
                    v[i] += __shfl_xor_sync(0xffffffffu, v[i], m);
            }
            if (lane < 4) {
                #pragma unroll
                for (int nt = 0; nt < 4; nt++) {
                    float2 o = {v[2 * nt], v[2 * nt + 1]};
                    *(float2*)(out + (size_t)node * 128 + n0 + nt * 8 + 2 * tg) = o;
                }
            }
        }
    }
}

extern "C" void kernel_launch(void* const* d_in, const int* in_sizes, int n_in,
                              void* d_out, int out_size)
{
    const float* src = (const float*)d_in[0];
    const float* he  = (const float*)d_in[1];
    const float* Wcf = (const float*)d_in[2];
    const float* bcf = (const float*)d_in[3];
    const float* Wdf = (const float*)d_in[4];
    const float* bdf = (const float*)d_in[5];
    const float* Wfc = (const float*)d_in[6];
    const float* bfc = (const float*)d_in[7];
    float* out = (float*)d_out;

    int ntiles = in_sizes[0] / 16384;   // 128 pairs (4 nodes) per tile

    int nsm = 148;
    cudaDeviceGetAttribute(&nsm, cudaDevAttrMultiProcessorCount, 0);
    int grid = nsm < ntiles ? nsm : ntiles;

    cudaFuncSetAttribute(dtnn_kernel, cudaFuncAttributeMaxDynamicSharedMemorySize,
                         (int)SMEM_BYTES);
    dtnn_kernel<<<grid, TPB, SMEM_BYTES>>>(src, he, Wcf, bcf, Wdf, bdf, Wfc, bfc,
                                           out, ntiles);
}

// round 15
// speedup vs baseline: 1.3039x; 1.0864x over previous
#include <cuda_runtime.h>
#include <cuda_fp16.h>
#include <cstdint>

#define TPB 512

// smem byte offsets
#define OF_WC   0u           // 32KB fp16 Wcf (128 rows x 256B, swizzled)
#define OF_WF   32768u       // 32KB fp16 Wfc
#define OF_WD   65536u       // 8KB fp16 Wdf (hoisted to regs at init)
#define OF_SRCq(q) (73728u  + (uint32_t)(q) * 8192u)   // fp16 src slice: 32x128
#define OF_HEq(q)  (106496u + (uint32_t)(q) * 2048u)   // fp16 he slice: 32x32
#define OF_Hq(q)   (114688u + (uint32_t)(q) * 8192u)   // fp16 h slice: 32x128
#define OF_SG(q)   (147456u + (uint32_t)(q) * 16384u)  // fp32 staging src
#define OF_SGH(q)  (212992u + (uint32_t)(q) * 4096u)   // fp32 staging he
#define OF_BC   229376u
#define OF_BD   229888u
#define OF_BF   230400u
#define OF_MB   230912u      // 4 x 8B mbarriers
#define SMEM_BYTES 230976u

__device__ __forceinline__ void ldsm4(uint32_t r[4], uint32_t a) {
    asm volatile("ldmatrix.sync.aligned.m8n8.x4.shared.b16 {%0,%1,%2,%3}, [%4];"
                 : "=r"(r[0]), "=r"(r[1]), "=r"(r[2]), "=r"(r[3]) : "r"(a));
}

__device__ __forceinline__ void stsm4(uint32_t a, uint32_t r0, uint32_t r1,
                                      uint32_t r2, uint32_t r3) {
    asm volatile("stmatrix.sync.aligned.m8n8.x4.shared.b16 [%0], {%1,%2,%3,%4};"
                 :: "r"(a), "r"(r0), "r"(r1), "r"(r2), "r"(r3) : "memory");
}

__device__ __forceinline__ void sts64(uint32_t a, uint32_t lo, uint32_t hi) {
    asm volatile("st.shared.v2.b32 [%0], {%1,%2};"
                 :: "r"(a), "r"(lo), "r"(hi) : "memory");
}

__device__ __forceinline__ void mma16(float* c, const uint32_t* a, uint32_t b0, uint32_t b1) {
    asm volatile(
        "mma.sync.aligned.m16n8k16.row.col.f32.f16.f16.f32 "
        "{%0,%1,%2,%3}, {%4,%5,%6,%7}, {%8,%9}, {%0,%1,%2,%3};\n"
        : "+f"(c[0]), "+f"(c[1]), "+f"(c[2]), "+f"(c[3])
        : "r"(a[0]), "r"(a[1]), "r"(a[2]), "r"(a[3]), "r"(b0), "r"(b1));
}

// f16-accumulator mma — GEMM2 only (K=32, bias preloaded into acc)
__device__ __forceinline__ void mma16h(uint32_t* c, const uint32_t* a, uint32_t b0, uint32_t b1) {
    asm volatile(
        "mma.sync.aligned.m16n8k16.row.col.f16.f16.f16.f16 "
        "{%0,%1}, {%2,%3,%4,%5}, {%6,%7}, {%0,%1};\n"
        : "+r"(c[0]), "+r"(c[1])
        : "r"(a[0]), "r"(a[1]), "r"(a[2]), "r"(a[3]), "r"(b0), "r"(b1));
}

__device__ __forceinline__ float ftanh(float x) {
    float r;
    asm("tanh.approx.f32 %0, %1;" : "=f"(r) : "f"(x));
    return r;
}

__device__ __forceinline__ uint32_t pack2(float a, float b) {
    __half2 h = __floats2half2_rn(a, b);
    return *(uint32_t*)&h;
}
__device__ __forceinline__ float2 unp2(uint32_t u) {
    __half2 h = *(__half2*)&u;
    return __half22float2(h);
}

__device__ __forceinline__ void qbar(int quad) {
    asm volatile("bar.sync %0, 128;" :: "r"(quad + 1) : "memory");
}

__device__ __forceinline__ void mb_init(uint32_t mbar, uint32_t cnt) {
    asm volatile("mbarrier.init.shared.b64 [%0], %1;" :: "r"(mbar), "r"(cnt) : "memory");
}
__device__ __forceinline__ void mb_expect(uint32_t mbar, uint32_t tx) {
    asm volatile("mbarrier.arrive.expect_tx.shared.b64 _, [%0], %1;"
                 :: "r"(mbar), "r"(tx) : "memory");
}
__device__ __forceinline__ void mb_wait(uint32_t mbar, uint32_t parity) {
    asm volatile("{\n\t.reg .pred P1;\n\t"
        "W_%=:\n\t"
        "mbarrier.try_wait.parity.acquire.cta.shared::cta.b64 P1, [%0], %1, 0x989680;\n\t"
        "@P1 bra.uni D_%=;\n\t"
        "bra.uni W_%=;\n\t"
        "D_%=:\n\t}"
        :: "r"(mbar), "r"(parity) : "memory");
}
__device__ __forceinline__ void bulk_g2s(uint32_t dst, const void* src,
                                         uint32_t bytes, uint32_t mbar) {
    asm volatile("cp.async.bulk.shared::cta.global.mbarrier::complete_tx::bytes "
                 "[%0], [%1], %2, [%3];"
                 :: "r"(dst), "l"(src), "r"(bytes), "r"(mbar) : "memory");
}
#define PROXY_FENCE() asm volatile("fence.proxy.async.shared::cta;" ::: "memory")

__device__ __forceinline__ uint32_t a16(uint32_t row, uint32_t ch) {
    return row * 256u + ((ch ^ (row & 7u)) << 4);
}
__device__ __forceinline__ uint32_t h16(uint32_t row, uint32_t ch) {
    return row * 64u + ((ch ^ ((row >> 1) & 3u)) << 4);
}

__global__ void __launch_bounds__(TPB, 1)
dtnn_kernel(const float* __restrict__ gsrc, const float* __restrict__ ghe,
            const float* __restrict__ Wcf,  const float* __restrict__ bcf,
            const float* __restrict__ Wdf,  const float* __restrict__ bdf,
            const float* __restrict__ Wfc,  const float* __restrict__ bfc,
            float* __restrict__ out, int ntiles)
{
    extern __shared__ __align__(1024) unsigned char sm[];
    uint32_t smb;
    asm("{.reg .u64 t; cvta.to.shared.u64 t, %1; cvt.u32.u64 %0, t;}"
        : "=r"(smb) : "l"(sm));

    float* bC = (float*)(sm + OF_BC);
    float* bD = (float*)(sm + OF_BD);
    float* bF = (float*)(sm + OF_BF);

    const int tid  = threadIdx.x;
    const int lane = tid & 31;
    const int wid  = tid >> 5;
    const int tg   = lane & 3;
    const int quad = wid >> 2;
    const int qtid = tid & 127;
    const int n0   = (wid & 3) * 32;
    const uint32_t mbar = smb + OF_MB + (uint32_t)quad * 8u;
    const int grid = gridDim.x;

    if (tid < 4) {
        mb_init(smb + OF_MB + (uint32_t)tid * 8u, 1u);
        PROXY_FENCE();
    }
    __syncthreads();

    if (qtid == 0) {
        mb_expect(mbar, 20480u);
        bulk_g2s(smb + OF_SG(quad), gsrc + (size_t)blockIdx.x * 16384 + quad * 4096,
                 16384u, mbar);
        bulk_g2s(smb + OF_SGH(quad), ghe + (size_t)blockIdx.x * 4096 + quad * 1024,
                 4096u, mbar);
    }

    for (int i = tid; i < 2048; i += TPB) {
        int row = i >> 4, ch = i & 15;
        float4 u = ((const float4*)Wcf)[row * 32 + ch * 2];
        float4 v = ((const float4*)Wcf)[row * 32 + ch * 2 + 1];
        uint4 w = {pack2(u.x, u.y), pack2(u.z, u.w), pack2(v.x, v.y), pack2(v.z, v.w)};
        *(uint4*)(sm + OF_WC + a16(row, ch)) = w;
        u = ((const float4*)Wfc)[row * 32 + ch * 2];
        v = ((const float4*)Wfc)[row * 32 + ch * 2 + 1];
        uint4 w2 = {pack2(u.x, u.y), pack2(u.z, u.w), pack2(v.x, v.y), pack2(v.z, v.w)};
        *(uint4*)(sm + OF_WF + a16(row, ch)) = w2;
    }
    for (int i = tid; i < 512; i += TPB) {
        int row = i >> 2, ch = i & 3;
        float4 u = ((const float4*)Wdf)[row * 8 + ch * 2];
        float4 v = ((const float4*)Wdf)[row * 8 + ch * 2 + 1];
        uint4 w = {pack2(u.x, u.y), pack2(u.z, u.w), pack2(v.x, v.y), pack2(v.z, v.w)};
        *(uint4*)(sm + OF_WD + h16(row, ch)) = w;
    }
    if (tid < 128) { bC[tid] = bcf[tid]; bD[tid] = bdf[tid]; bF[tid] = bfc[tid]; }
    __syncthreads();

    const uint32_t mrow = (uint32_t)((lane & 7) | (((lane >> 3) & 1) << 3));
    const uint32_t ksel = (uint32_t)((lane >> 4) & 1);
    const uint32_t key8 = mrow & 7u;
    const uint32_t keyh = (mrow >> 1) & 3u;

    const uint32_t srcB = smb + OF_SRCq(quad) + mrow * 256u;
    const uint32_t heB  = smb + OF_HEq(quad) + mrow * 64u;
    const uint32_t hBa  = smb + OF_Hq(quad) + mrow * 256u;
    const uint32_t hBst = smb + OF_Hq(quad);
    const uint32_t wc0  = smb + OF_WC + ((uint32_t)n0 + mrow) * 256u;
    const uint32_t wf0  = smb + OF_WF + ((uint32_t)n0 + mrow) * 256u;
    uint32_t wdr[2][2][4];
    {
        uint32_t wdB[2];
        #pragma unroll
        for (int p = 0; p < 2; p++)
            wdB[p] = smb + OF_WD + ((uint32_t)(n0 + 16 * p) + mrow) * 64u;
        #pragma unroll
        for (int kt = 0; kt < 2; kt++) {
            uint32_t ub = ((2u * kt + ksel) ^ keyh) << 4;
            ldsm4(wdr[kt][0], wdB[0] + ub);
            ldsm4(wdr[kt][1], wdB[1] + ub);
        }
    }
    const uint32_t srow = (uint32_t)(((lane >> 4) & 1) * 16 + ((lane >> 3) & 1) * 8
                                     + (lane & 7));

    uint32_t ph = 0;

    for (int tile = blockIdx.x; tile < ntiles; tile += grid) {
        // 1. bulk staging complete (safety vs prev tile is carried by the
        //    gate-qbar of the previous iteration — no top barrier needed)
        mb_wait(mbar, ph); ph ^= 1;

        // 2. convert: full-density LDS.128 (contiguous lanes) + swizzled STS.64
        {
            const float4* sg = (const float4*)(sm + OF_SG(quad));
            #pragma unroll
            for (int it = 0; it < 8; it++) {
                int i = qtid + it * 128;                 // 1024 fp32 16B chunks
                uint32_t row = (uint32_t)(i >> 5);
                uint32_t c8  = (uint32_t)(i & 31);       // 8B output granule
                float4 u = sg[i];
                uint32_t off = row * 256u + (((c8 >> 1) ^ (row & 7u)) << 4)
                             + (c8 & 1u) * 8u;
                sts64(smb + OF_SRCq(quad) + off, pack2(u.x, u.y), pack2(u.z, u.w));
            }
            const float4* sh = (const float4*)(sm + OF_SGH(quad));
            #pragma unroll
            for (int it = 0; it < 2; it++) {
                int i = qtid + it * 128;                 // 256 fp32 16B chunks
                uint32_t row = (uint32_t)(i >> 3);
                uint32_t c8  = (uint32_t)(i & 7);
                float4 u = sh[i];
                uint32_t off = row * 64u + (((c8 >> 1) ^ ((row >> 1) & 3u)) << 4)
                             + (c8 & 1u) * 8u;
                sts64(smb + OF_HEq(quad) + off, pack2(u.x, u.y), pack2(u.z, u.w));
            }
        }
        qbar(quad);    // fp16 tiles visible; staging buffer free; prev GEMM3 done

        if (qtid == 0 && tile + grid < ntiles) {
            int nt_ = tile + grid;
            PROXY_FENCE();
            mb_expect(mbar, 20480u);
            bulk_g2s(smb + OF_SG(quad), gsrc + (size_t)nt_ * 16384 + quad * 4096,
                     16384u, mbar);
            bulk_g2s(smb + OF_SGH(quad), ghe + (size_t)nt_ * 4096 + quad * 1024,
                     4096u, mbar);
        }

        // GEMM2 (f16 acc, bias preloaded)
        uint32_t accEp[2][4][2];
        #pragma unroll
        for (int nt = 0; nt < 4; nt++) {
            int c = n0 + nt * 8 + 2 * tg;
            float2 bd2 = *(float2*)(bD + c);
            uint32_t bini = pack2(bd2.x, bd2.y);
            accEp[0][nt][0] = bini; accEp[0][nt][1] = bini;
            accEp[1][nt][0] = bini; accEp[1][nt][1] = bini;
        }
        #pragma unroll
        for (int kt = 0; kt < 2; kt++) {
            uint32_t ua = ((2u * kt + ksel) ^ keyh) << 4;
            uint32_t A0[4], A1[4];
            ldsm4(A0, heB + ua);
            ldsm4(A1, heB + 1024u + ua);
            #pragma unroll
            for (int p = 0; p < 2; p++) {
                mma16h(accEp[0][2 * p],     A0, wdr[kt][p][0], wdr[kt][p][2]);
                mma16h(accEp[0][2 * p + 1], A0, wdr[kt][p][1], wdr[kt][p][3]);
                mma16h(accEp[1][2 * p],     A1, wdr[kt][p][0], wdr[kt][p][2]);
                mma16h(accEp[1][2 * p + 1], A1, wdr[kt][p][1], wdr[kt][p][3]);
            }
        }

        // GEMM1
        float accC[2][4][4];
        #pragma unroll
        for (int mt = 0; mt < 2; mt++)
            #pragma unroll
            for (int nt = 0; nt < 4; nt++)
                accC[mt][nt][0] = accC[mt][nt][1] = accC[mt][nt][2] = accC[mt][nt][3] = 0.f;
        #pragma unroll
        for (int kt = 0; kt < 8; kt++) {
            uint32_t ua = ((2u * kt + ksel) ^ key8) << 4;
            uint32_t A0[4], A1[4], B0[4], B1[4];
            ldsm4(A0, srcB + ua);
            ldsm4(A1, srcB + 4096u + ua);
            ldsm4(B0, wc0 + ua);
            ldsm4(B1, wc0 + 4096u + ua);
            mma16(accC[0][0], A0, B0[0], B0[2]);
            mma16(accC[0][1], A0, B0[1], B0[3]);
            mma16(accC[0][2], A0, B1[0], B1[2]);
            mma16(accC[0][3], A0, B1[1], B1[3]);
            mma16(accC[1][0], A1, B0[0], B0[2]);
            mma16(accC[1][1], A1, B0[1], B0[3]);
            mma16(accC[1][2], A1, B1[0], B1[2]);
            mma16(accC[1][3], A1, B1[1], B1[3]);
        }

        // gate -> h buffer
        #pragma unroll
        for (int nt = 0; nt < 4; nt++) {
            int c = n0 + nt * 8 + 2 * tg;
            float2 bc2 = *(float2*)(bC + c);
            float2 e00 = unp2(accEp[0][nt][0]);
            float2 e01 = unp2(accEp[0][nt][1]);
            float2 e10 = unp2(accEp[1][nt][0]);
            float2 e11 = unp2(accEp[1][nt][1]);
            uint32_t p0 = pack2((accC[0][nt][0] + bc2.x) * e00.x,
                                (accC[0][nt][1] + bc2.y) * e00.y);
            uint32_t p1 = pack2((accC[0][nt][2] + bc2.x) * e01.x,
                                (accC[0][nt][3] + bc2.y) * e01.y);
            uint32_t p2 = pack2((accC[1][nt][0] + bc2.x) * e10.x,
                                (accC[1][nt][1] + bc2.y) * e10.y);
            uint32_t p3 = pack2((accC[1][nt][2] + bc2.x) * e11.x,
                                (accC[1][nt][3] + bc2.y) * e11.y);
            uint32_t ch = (uint32_t)(n0 >> 3) + (uint32_t)nt;
            stsm4(hBst + a16(srow, ch), p0, p1, p2, p3);
        }
        qbar(quad);    // h visible; all quad warps past GEMM1/GEMM2 reads

        // GEMM3
        #pragma unroll
        for (int mt = 0; mt < 2; mt++)
            #pragma unroll
            for (int nt = 0; nt < 4; nt++)
                accC[mt][nt][0] = accC[mt][nt][1] = accC[mt][nt][2] = accC[mt][nt][3] = 0.f;
        #pragma unroll
        for (int kt = 0; kt < 8; kt++) {
            uint32_t ua = ((2u * kt + ksel) ^ key8) << 4;
            uint32_t A0[4], A1[4], B0[4], B1[4];
            ldsm4(A0, hBa + ua);
            ldsm4(A1, hBa + 4096u + ua);
            ldsm4(B0, wf0 + ua);
            ldsm4(B1, wf0 + 4096u + ua);
            mma16(accC[0][0], A0, B0[0], B0[2]);
            mma16(accC[0][1], A0, B0[1], B0[3]);
            mma16(accC[0][2], A0, B1[0], B1[2]);
            mma16(accC[0][3], A0, B1[1], B1[3]);
            mma16(accC[1][0], A1, B0[0], B0[2]);
            mma16(accC[1][1], A1, B0[1], B0[3]);
            mma16(accC[1][2], A1, B1[0], B1[2]);
            mma16(accC[1][3], A1, B1[1], B1[3]);
        }

        // epilogue
        {
            const int node = tile * 4 + quad;
            float v[8];
            #pragma unroll
            for (int nt = 0; nt < 4; nt++) {
                int c = n0 + nt * 8 + 2 * tg;
                float2 bf2 = *(float2*)(bF + c);
                v[2 * nt]     = ftanh(accC[0][nt][0] + bf2.x) + ftanh(accC[0][nt][2] + bf2.x)
                              + ftanh(accC[1][nt][0] + bf2.x) + ftanh(accC[1][nt][2] + bf2.x);
                v[2 * nt + 1] = ftanh(accC[0][nt][1] + bf2.y) + ftanh(accC[0][nt][3] + bf2.y)
                              + ftanh(accC[1][nt][1] + bf2.y) + ftanh(accC[1][nt][3] + bf2.y);
            }
            #pragma unroll
            for (int m = 4; m < 32; m <<= 1) {
                #pragma unroll
                for (int i = 0; i < 8; i++)
                    v[i] += __shfl_xor_sync(0xffffffffu, v[i], m);
            }
            if (lane < 4) {
                #pragma unroll
                for (int nt = 0; nt < 4; nt++) {
                    float2 o = {v[2 * nt], v[2 * nt + 1]};
                    *(float2*)(out + (size_t)node * 128 + n0 + nt * 8 + 2 * tg) = o;
                }
            }
        }
    }
}

extern "C" void kernel_launch(void* const* d_in, const int* in_sizes, int n_in,
                              void* d_out, int out_size)
{
    const float* src = (const float*)d_in[0];
    const float* he  = (const float*)d_in[1];
    const float* Wcf = (const float*)d_in[2];
    const float* bcf = (const float*)d_in[3];
    const float* Wdf = (const float*)d_in[4];
    const float* bdf = (const float*)d_in[5];
    const float* Wfc = (const float*)d_in[6];
    const float* bfc = (const float*)d_in[7];
    float* out = (float*)d_out;

    int ntiles = in_sizes[0] / 16384;   // 128 pairs (4 nodes) per tile

    int nsm = 148;
    cudaDeviceGetAttribute(&nsm, cudaDevAttrMultiProcessorCount, 0);
    int grid = nsm < ntiles ? nsm : ntiles;

    cudaFuncSetAttribute(dtnn_kernel, cudaFuncAttributeMaxDynamicSharedMemorySize,
                         (int)SMEM_BYTES);
    dtnn_kernel<<<grid, TPB, SMEM_BYTES>>>(src, he, Wcf, bcf, Wdf, bdf, Wfc, bfc,
                                           out, ntiles);
}